// round 5
// baseline (speedup 1.0000x reference)
#include <cuda_runtime.h>
#include <math.h>
#include <stdint.h>

#define N_DIM 4096
#define B_DIM 512
#define NB 128
#define NPAN (N_DIM / NB)

// ---------------- device scratch (static __device__ arrays: allowed) -------
__device__ float g_M[(size_t)N_DIM * N_DIM];      // 64 MB: M, overwritten by L
__device__ float g_Linv[NPAN * NB * NB];          // 2 MB: inverses of diag blocks
__device__ float g_Z[(size_t)B_DIM * N_DIM];      // 8 MB: solution / workspace
__device__ float g_R[(size_t)B_DIM * N_DIM];      // 8 MB: residual / correction
__device__ float g_scal[4];                       // c1, c2

// ---------------- scalars: c1=(||imp||^2+||exc||^2)/B, c2=gamma/B ----------
__global__ void scalars_kernel(const float* __restrict__ imp,
                               const float* __restrict__ exc,
                               const float* __restrict__ gamma_p) {
    __shared__ float red[32];
    int tid = threadIdx.x;  // 1024 threads
    float v = imp[tid] * imp[tid] + exc[tid] * exc[tid];
    #pragma unroll
    for (int o = 16; o > 0; o >>= 1) v += __shfl_down_sync(0xffffffffu, v, o);
    if ((tid & 31) == 0) red[tid >> 5] = v;
    __syncthreads();
    if (tid < 32) {
        float s = red[tid];
        #pragma unroll
        for (int o = 16; o > 0; o >>= 1) s += __shfl_down_sync(0xffffffffu, s, o);
        if (tid == 0) {
            g_scal[0] = s / (float)B_DIM;
            g_scal[1] = gamma_p[0] / (float)B_DIM;
        }
    }
}

// ---------------- build M = c1*Phi + c2*I ---------------------------------
__global__ void build_M_kernel(const float* __restrict__ Phi) {
    const float c1 = g_scal[0], c2 = g_scal[1];
    size_t total = (size_t)N_DIM * N_DIM;
    for (size_t i = (size_t)blockIdx.x * blockDim.x + threadIdx.x; i < total;
         i += (size_t)gridDim.x * blockDim.x) {
        float v = c1 * Phi[i];
        if ((i >> 12) == (i & 4095)) v += c2;
        g_M[i] = v;
    }
}

// ---------------- generic copy / add --------------------------------------
__global__ void copy_kernel(float* __restrict__ dst, const float* __restrict__ src,
                            size_t n4) {
    for (size_t i = (size_t)blockIdx.x * blockDim.x + threadIdx.x; i < n4;
         i += (size_t)gridDim.x * blockDim.x) {
        reinterpret_cast<float4*>(dst)[i] = reinterpret_cast<const float4*>(src)[i];
    }
}
__global__ void add_kernel(float* __restrict__ dst, const float* __restrict__ src,
                           size_t n4) {
    for (size_t i = (size_t)blockIdx.x * blockDim.x + threadIdx.x; i < n4;
         i += (size_t)gridDim.x * blockDim.x) {
        float4 a = reinterpret_cast<float4*>(dst)[i];
        float4 b = reinterpret_cast<const float4*>(src)[i];
        a.x += b.x; a.y += b.y; a.z += b.z; a.w += b.w;
        reinterpret_cast<float4*>(dst)[i] = a;
    }
}

// ---------------- 128x128 diag block: Cholesky + IN-PLACE inverse ----------
// 1 block, 128 threads, dynamic smem = 128*129 floats (~66 KB)
__global__ void chol_diag_kernel(int k) {
    extern __shared__ float sh[];
    float* s = sh;                  // [128][129] workspace (L, then L^{-1})
    const int tid = threadIdx.x;
    float* blk = &g_M[(size_t)(k * NB) * N_DIM + (size_t)k * NB];

    #pragma unroll 4
    for (int j = 0; j < NB; j++) s[tid * 129 + j] = blk[(size_t)tid * N_DIM + j];
    __syncthreads();

    // unblocked Cholesky (lower)
    for (int j = 0; j < NB; j++) {
        if (tid == j) s[j * 129 + j] = sqrtf(s[j * 129 + j]);
        __syncthreads();
        float dinv = 1.0f / s[j * 129 + j];
        if (tid > j) s[tid * 129 + j] *= dinv;
        __syncthreads();
        if (tid > j) {
            float lij = s[tid * 129 + j];
            for (int c = j + 1; c <= tid; c++)
                s[tid * 129 + c] -= lij * s[c * 129 + j];
        }
        __syncthreads();
    }
    // write L back (lower triangle only; upper junk never read)
    for (int j = 0; j <= tid; j++) blk[(size_t)tid * N_DIM + j] = s[tid * 129 + j];
    __syncthreads();

    // in-place triangular inverse: row sweep, thread tid owns column c = tid.
    // inv[j][c] = (delta_jc - sum_{p=c}^{j-1} L[j][p]*inv[p][c]) / L[j][j]
    // rows p<j already hold inverse entries; row j still holds L until written.
    const int c = tid;
    for (int j = 0; j < NB; j++) {
        float val = 0.0f;
        if (c <= j) {
            float sum = (j == c) ? 1.0f : 0.0f;
            for (int p = c; p < j; p++) sum -= s[j * 129 + p] * s[p * 129 + c];
            val = sum / s[j * 129 + j];
        }
        __syncthreads();              // all reads of L row j complete
        if (c <= j) s[j * 129 + c] = val;
        __syncthreads();              // inverse row j visible
    }
    float* go = &g_Linv[(size_t)k * NB * NB];
    for (int j = 0; j < NB; j++)
        go[j * NB + c] = (j >= c) ? s[j * 129 + c] : 0.0f;
}

// ---------------- tiled fp32 GEMM, 128x128 output tile, K step 16 ----------
// BT=1: C op= A(MxK) * B(NxK)^T     BT=0: C op= A(MxK) * B(KxN)
// MODE 0: C -= AB   MODE 1: C = AB   MODE 2: C = D - c1*AB - c2*E (residual)
// All of M, N multiples of 128; K multiple of 16. triSkip: skip tiles above diag.
template <int BT, int MODE>
__global__ __launch_bounds__(256)
void gemm_kernel(const float* __restrict__ A, int lda,
                 const float* __restrict__ B, int ldb,
                 float* __restrict__ C, int ldc, int K, int triSkip,
                 const float* __restrict__ D,
                 const float* __restrict__ E) {
    const int bx = blockIdx.x, by = blockIdx.y;
    if (triSkip && by < bx) return;
    const int r0 = by * 128, c0 = bx * 128;

    __shared__ float As[16][132];
    __shared__ float Bs[16][132];

    const int tid = threadIdx.x;        // 256
    const int tx = tid & 15, ty = tid >> 4;
    const int ai = tid >> 1;            // row within tile (0..127)
    const int aw = (tid & 1) << 3;      // which 8-wide k chunk (0 or 8)

    float acc[8][8];
    #pragma unroll
    for (int i = 0; i < 8; i++)
        #pragma unroll
        for (int j = 0; j < 8; j++) acc[i][j] = 0.0f;

    for (int k0 = 0; k0 < K; k0 += 16) {
        float4 av0 = *reinterpret_cast<const float4*>(
            &A[(size_t)(r0 + ai) * lda + k0 + aw]);
        float4 av1 = *reinterpret_cast<const float4*>(
            &A[(size_t)(r0 + ai) * lda + k0 + aw + 4]);
        float4 bv0, bv1;
        if (BT) {
            bv0 = *reinterpret_cast<const float4*>(
                &B[(size_t)(c0 + ai) * ldb + k0 + aw]);
            bv1 = *reinterpret_cast<const float4*>(
                &B[(size_t)(c0 + ai) * ldb + k0 + aw + 4]);
        } else {
            bv0 = *reinterpret_cast<const float4*>(
                &B[(size_t)(k0 + (tid >> 5)) * ldb + c0 + ((tid & 31) << 2)]);
            bv1 = *reinterpret_cast<const float4*>(
                &B[(size_t)(k0 + 8 + (tid >> 5)) * ldb + c0 + ((tid & 31) << 2)]);
        }
        __syncthreads();
        As[aw + 0][ai] = av0.x; As[aw + 1][ai] = av0.y;
        As[aw + 2][ai] = av0.z; As[aw + 3][ai] = av0.w;
        As[aw + 4][ai] = av1.x; As[aw + 5][ai] = av1.y;
        As[aw + 6][ai] = av1.z; As[aw + 7][ai] = av1.w;
        if (BT) {
            Bs[aw + 0][ai] = bv0.x; Bs[aw + 1][ai] = bv0.y;
            Bs[aw + 2][ai] = bv0.z; Bs[aw + 3][ai] = bv0.w;
            Bs[aw + 4][ai] = bv1.x; Bs[aw + 5][ai] = bv1.y;
            Bs[aw + 6][ai] = bv1.z; Bs[aw + 7][ai] = bv1.w;
        } else {
            *reinterpret_cast<float4*>(&Bs[tid >> 5][(tid & 31) << 2]) = bv0;
            *reinterpret_cast<float4*>(&Bs[(tid >> 5) + 8][(tid & 31) << 2]) = bv1;
        }
        __syncthreads();
        #pragma unroll
        for (int kk = 0; kk < 16; kk++) {
            float4 a0 = *reinterpret_cast<const float4*>(&As[kk][ty * 8]);
            float4 a1 = *reinterpret_cast<const float4*>(&As[kk][ty * 8 + 4]);
            float4 b0 = *reinterpret_cast<const float4*>(&Bs[kk][tx * 8]);
            float4 b1 = *reinterpret_cast<const float4*>(&Bs[kk][tx * 8 + 4]);
            float a[8] = {a0.x, a0.y, a0.z, a0.w, a1.x, a1.y, a1.z, a1.w};
            float b[8] = {b0.x, b0.y, b0.z, b0.w, b1.x, b1.y, b1.z, b1.w};
            #pragma unroll
            for (int i = 0; i < 8; i++)
                #pragma unroll
                for (int j = 0; j < 8; j++) acc[i][j] += a[i] * b[j];
        }
    }

    float c1 = 0.0f, c2 = 0.0f;
    if (MODE == 2) { c1 = g_scal[0]; c2 = g_scal[1]; }
    #pragma unroll
    for (int i = 0; i < 8; i++) {
        size_t base = (size_t)(r0 + ty * 8 + i) * ldc + c0 + tx * 8;
        #pragma unroll
        for (int j = 0; j < 8; j++) {
            if (MODE == 0) C[base + j] -= acc[i][j];
            else if (MODE == 1) C[base + j] = acc[i][j];
            else C[base + j] = D[base + j] - c1 * acc[i][j] - c2 * E[base + j];
        }
    }
}

// ---------------- finish: denom_i = a * <z_i, k_i>; out = z / denom --------
__global__ void finish_kernel(const float* __restrict__ Kb,
                              const float* __restrict__ a_p,
                              float* __restrict__ out) {
    const int row = blockIdx.x;
    const float* z = &g_Z[(size_t)row * N_DIM];
    const float* kk = &Kb[(size_t)row * N_DIM];
    __shared__ float red[8];
    __shared__ float dsh;
    int tid = threadIdx.x;  // 256
    float s = 0.0f;
    for (int j = tid; j < N_DIM; j += 256) s += z[j] * kk[j];
    #pragma unroll
    for (int o = 16; o > 0; o >>= 1) s += __shfl_down_sync(0xffffffffu, s, o);
    if ((tid & 31) == 0) red[tid >> 5] = s;
    __syncthreads();
    if (tid == 0) {
        float t = 0.0f;
        #pragma unroll
        for (int w = 0; w < 8; w++) t += red[w];
        dsh = 1.0f / (a_p[0] * t);
    }
    __syncthreads();
    float d = dsh;
    for (int j = tid; j < N_DIM; j += 256)
        out[(size_t)row * N_DIM + j] = z[j] * d;
}

// ---------------- host orchestration --------------------------------------
static void solve_inplace(float* X, float* pM, float* pLinv) {
    // forward: X := X * L^{-T}  (right-looking over column blocks)
    for (int j = 0; j < NPAN; j++) {
        float* Xj = X + j * NB;
        dim3 g(1, B_DIM / NB);
        gemm_kernel<1, 1><<<g, 256>>>(Xj, N_DIM, pLinv + (size_t)j * NB * NB, NB,
                                      Xj, N_DIM, NB, 0, nullptr, nullptr);
        int ncols = N_DIM - (j + 1) * NB;
        if (ncols > 0) {
            float* Xt = X + (j + 1) * NB;
            const float* Bp = pM + (size_t)(j + 1) * NB * N_DIM + (size_t)j * NB;
            dim3 g2(ncols / NB, B_DIM / NB);
            gemm_kernel<1, 0><<<g2, 256>>>(Xj, N_DIM, Bp, N_DIM, Xt, N_DIM, NB, 0,
                                           nullptr, nullptr);
        }
    }
    // backward: X := X * L^{-1}
    for (int j = NPAN - 1; j >= 0; j--) {
        float* Xj = X + j * NB;
        dim3 g(1, B_DIM / NB);
        gemm_kernel<0, 1><<<g, 256>>>(Xj, N_DIM, pLinv + (size_t)j * NB * NB, NB,
                                      Xj, N_DIM, NB, 0, nullptr, nullptr);
        if (j > 0) {
            const float* Bp = pM + (size_t)j * NB * N_DIM;  // L[jblk, 0:j*NB], NN
            dim3 g2(j, B_DIM / NB);
            gemm_kernel<0, 0><<<g2, 256>>>(Xj, N_DIM, Bp, N_DIM, X, N_DIM, NB, 0,
                                           nullptr, nullptr);
        }
    }
}

extern "C" void kernel_launch(void* const* d_in, const int* in_sizes, int n_in,
                              void* d_out, int out_size) {
    // Bind inputs BY SIZE (robust to metadata ordering):
    //   16.7M elems -> Phi, 2.1M -> K_batch, 1024 -> imp/exc (interchangeable:
    //   only ||.||^2 sums are used), scalars in encounter order -> a, gamma.
    const float* Kb = nullptr;
    const float* Phi = nullptr;
    const float* v1024a = nullptr;
    const float* v1024b = nullptr;
    const float* a_p = nullptr;
    const float* gam = nullptr;
    for (int i = 0; i < n_in; i++) {
        int sz = in_sizes[i];
        const float* p = (const float*)d_in[i];
        if (sz == N_DIM * N_DIM) Phi = p;
        else if (sz == B_DIM * N_DIM) Kb = p;
        else if (sz == 1024) { if (!v1024a) v1024a = p; else v1024b = p; }
        else if (sz == 1) { if (!a_p) a_p = p; else gam = p; }
    }
    (void)out_size;

    const int dynSmem = 128 * 129 * (int)sizeof(float);  // ~66 KB
    cudaFuncSetAttribute(chol_diag_kernel,
                         cudaFuncAttributeMaxDynamicSharedMemorySize, dynSmem);

    float *pM, *pLinv, *pZ, *pR;
    cudaGetSymbolAddress((void**)&pM, g_M);
    cudaGetSymbolAddress((void**)&pLinv, g_Linv);
    cudaGetSymbolAddress((void**)&pZ, g_Z);
    cudaGetSymbolAddress((void**)&pR, g_R);

    scalars_kernel<<<1, 1024>>>(v1024a, v1024b, gam);
    build_M_kernel<<<4096, 256>>>(Phi);

    // blocked right-looking Cholesky (L in lower triangle of g_M)
    for (int k = 0; k < NPAN; k++) {
        chol_diag_kernel<<<1, 128, dynSmem>>>(k);
        int rows = N_DIM - (k + 1) * NB;
        if (rows > 0) {
            float* A21 = pM + (size_t)(k + 1) * NB * N_DIM + (size_t)k * NB;
            dim3 gp(1, rows / NB);   // panel: L21 = A21 * Linv_k^T (in place)
            gemm_kernel<1, 1><<<gp, 256>>>(A21, N_DIM,
                                           pLinv + (size_t)k * NB * NB, NB, A21,
                                           N_DIM, NB, 0, nullptr, nullptr);
            float* C22 = pM + (size_t)(k + 1) * NB * N_DIM + (size_t)(k + 1) * NB;
            dim3 gs(rows / NB, rows / NB);  // SYRK (lower tiles only)
            gemm_kernel<1, 0><<<gs, 256>>>(A21, N_DIM, A21, N_DIM, C22, N_DIM,
                                           NB, 1, nullptr, nullptr);
        }
    }

    // Z = K; Z := Z * L^{-T} * L^{-1}  (rows of Z are the per-sample solutions)
    size_t n4 = (size_t)B_DIM * N_DIM / 4;
    copy_kernel<<<1024, 256>>>(pZ, Kb, n4);
    solve_inplace(pZ, pM, pLinv);

    // one iterative-refinement step: R = K - c1*Z@Phi - c2*Z; solve; Z += E
    {
        dim3 g(N_DIM / NB, B_DIM / NB);
        gemm_kernel<0, 2><<<g, 256>>>(pZ, N_DIM, Phi, N_DIM, pR, N_DIM, N_DIM, 0,
                                      Kb, pZ);
    }
    solve_inplace(pR, pM, pLinv);
    add_kernel<<<1024, 256>>>(pZ, pR, n4);

    finish_kernel<<<B_DIM, 256>>>(Kb, a_p, (float*)d_out);
}

// round 7
// speedup vs baseline: 1.5899x; 1.5899x over previous
#include <cuda_runtime.h>
#include <math.h>
#include <stdint.h>

#define N_DIM 4096
#define B_DIM 512
#define NB 128
#define NPAN (N_DIM / NB)

// ---------------- device scratch (same footprint as round-5 pass) ----------
__device__ float g_M[(size_t)N_DIM * N_DIM];      // 64 MB: M -> L -> F(lower)/G(upper)
__device__ float g_Linv[NPAN * NB * NB];          // 2 MB: diag-block inverses
__device__ float g_X1[(size_t)B_DIM * N_DIM];     // 8 MB workspaces
__device__ float g_X2[(size_t)B_DIM * N_DIM];
__device__ float g_X3[(size_t)B_DIM * N_DIM];
__device__ float g_scal[4];                       // c1, c2

// ---------------- scalars: c1=(||imp||^2+||exc||^2)/B, c2=gamma/B ----------
__global__ void scalars_kernel(const float* __restrict__ imp,
                               const float* __restrict__ exc,
                               const float* __restrict__ gamma_p) {
    __shared__ float red[32];
    int tid = threadIdx.x;  // 1024
    float v = imp[tid] * imp[tid] + exc[tid] * exc[tid];
    #pragma unroll
    for (int o = 16; o > 0; o >>= 1) v += __shfl_down_sync(0xffffffffu, v, o);
    if ((tid & 31) == 0) red[tid >> 5] = v;
    __syncthreads();
    if (tid < 32) {
        float s = red[tid];
        #pragma unroll
        for (int o = 16; o > 0; o >>= 1) s += __shfl_down_sync(0xffffffffu, s, o);
        if (tid == 0) {
            g_scal[0] = s / (float)B_DIM;
            g_scal[1] = gamma_p[0] / (float)B_DIM;
        }
    }
}

// ---------------- build M = c1*Phi + c2*I ---------------------------------
__global__ void build_M_kernel(const float* __restrict__ Phi) {
    const float c1 = g_scal[0], c2 = g_scal[1];
    size_t total = (size_t)N_DIM * N_DIM;
    for (size_t i = (size_t)blockIdx.x * blockDim.x + threadIdx.x; i < total;
         i += (size_t)gridDim.x * blockDim.x) {
        float v = c1 * Phi[i];
        if ((i >> 12) == (i & 4095)) v += c2;
        g_M[i] = v;
    }
}

__global__ void copy_kernel(float* __restrict__ dst, const float* __restrict__ src,
                            size_t n4) {
    for (size_t i = (size_t)blockIdx.x * blockDim.x + threadIdx.x; i < n4;
         i += (size_t)gridDim.x * blockDim.x) {
        reinterpret_cast<float4*>(dst)[i] = reinterpret_cast<const float4*>(src)[i];
    }
}

// ---------------- 128x128 diag block: Cholesky + in-place inverse ----------
// 1 block, 1024 threads, dynamic smem = 128*129 floats (~66 KB)
__global__ void chol_diag_kernel(int k) {
    extern __shared__ float s[];    // [128][129]
    const int tid = threadIdx.x;
    float* blk = &g_M[(size_t)(k * NB) * N_DIM + (size_t)k * NB];

    for (int idx = tid; idx < NB * NB; idx += 1024) {
        int r = idx >> 7, c = idx & 127;
        s[r * 129 + c] = blk[(size_t)r * N_DIM + c];
    }
    __syncthreads();

    // Cholesky: column j scaled by rsqrt(d); diag left un-sqrted until fixup.
    const int ui = tid >> 3, ulane = tid & 7;
    for (int j = 0; j < NB; j++) {
        float v = s[j * 129 + j];          // read-only this iteration
        float rs = rsqrtf(v);
        if (tid < NB && tid > j) s[tid * 129 + j] *= rs;
        __syncthreads();
        if (ui > j) {
            float lij = s[ui * 129 + j];
            for (int c = j + 1 + ulane; c <= ui; c += 8)
                s[ui * 129 + c] -= lij * s[c * 129 + j];
        }
        __syncthreads();
    }
    if (tid < NB) s[tid * 129 + tid] = sqrtf(s[tid * 129 + tid]);
    __syncthreads();

    // write L back (full block; upper junk never read before fg overwrites)
    for (int idx = tid; idx < NB * NB; idx += 1024) {
        int r = idx >> 7, c = idx & 127;
        blk[(size_t)r * N_DIM + c] = s[r * 129 + c];
    }

    // in-place inverse: 8 lanes per column, row sweep.
    const int c8 = tid >> 3, lane = tid & 7;
    for (int j = 0; j < NB; j++) {
        float sum = 0.0f;
        for (int p = c8 + lane; p < j; p += 8)
            sum += s[j * 129 + p] * s[p * 129 + c8];
        sum += __shfl_down_sync(0xffffffffu, sum, 4, 8);
        sum += __shfl_down_sync(0xffffffffu, sum, 2, 8);
        sum += __shfl_down_sync(0xffffffffu, sum, 1, 8);
        float val = (((j == c8) ? 1.0f : 0.0f) - sum) / s[j * 129 + j];
        __syncthreads();
        if (c8 <= j && lane == 0) s[j * 129 + c8] = val;
        __syncthreads();
    }
    float* go = &g_Linv[(size_t)k * NB * NB];
    for (int idx = tid; idx < NB * NB; idx += 1024) {
        int r = idx >> 7, c = idx & 127;
        go[idx] = (r >= c) ? s[r * 129 + c] : 0.0f;
    }
}

// ---------------- shared 128x128x128 tile microkernel ----------------------
// BT=1: acc += A(128x128) * B(128x128)^T ; BT=0: acc += A * B.
template <int BT>
__device__ __forceinline__ void tile_gemm128(const float* __restrict__ A, int lda,
                                             const float* __restrict__ B, int ldb,
                                             float acc[8][8]) {
    __shared__ float As[16][132];
    __shared__ float Bs[16][132];
    const int tid = threadIdx.x;        // 256
    const int ai = tid >> 1;
    const int aw = (tid & 1) << 3;
    #pragma unroll 1
    for (int k0 = 0; k0 < 128; k0 += 16) {
        float4 av0 = *reinterpret_cast<const float4*>(&A[(size_t)ai * lda + k0 + aw]);
        float4 av1 = *reinterpret_cast<const float4*>(&A[(size_t)ai * lda + k0 + aw + 4]);
        float4 bv0, bv1;
        if (BT) {
            bv0 = *reinterpret_cast<const float4*>(&B[(size_t)ai * ldb + k0 + aw]);
            bv1 = *reinterpret_cast<const float4*>(&B[(size_t)ai * ldb + k0 + aw + 4]);
        } else {
            bv0 = *reinterpret_cast<const float4*>(
                &B[(size_t)(k0 + (tid >> 5)) * ldb + ((tid & 31) << 2)]);
            bv1 = *reinterpret_cast<const float4*>(
                &B[(size_t)(k0 + 8 + (tid >> 5)) * ldb + ((tid & 31) << 2)]);
        }
        __syncthreads();
        As[aw + 0][ai] = av0.x; As[aw + 1][ai] = av0.y;
        As[aw + 2][ai] = av0.z; As[aw + 3][ai] = av0.w;
        As[aw + 4][ai] = av1.x; As[aw + 5][ai] = av1.y;
        As[aw + 6][ai] = av1.z; As[aw + 7][ai] = av1.w;
        if (BT) {
            Bs[aw + 0][ai] = bv0.x; Bs[aw + 1][ai] = bv0.y;
            Bs[aw + 2][ai] = bv0.z; Bs[aw + 3][ai] = bv0.w;
            Bs[aw + 4][ai] = bv1.x; Bs[aw + 5][ai] = bv1.y;
            Bs[aw + 6][ai] = bv1.z; Bs[aw + 7][ai] = bv1.w;
        } else {
            *reinterpret_cast<float4*>(&Bs[tid >> 5][(tid & 31) << 2]) = bv0;
            *reinterpret_cast<float4*>(&Bs[(tid >> 5) + 8][(tid & 31) << 2]) = bv1;
        }
        __syncthreads();
        #pragma unroll
        for (int kk = 0; kk < 16; kk++) {
            float4 a0 = *reinterpret_cast<const float4*>(&As[kk][(tid >> 4) * 8]);
            float4 a1 = *reinterpret_cast<const float4*>(&As[kk][(tid >> 4) * 8 + 4]);
            float4 b0 = *reinterpret_cast<const float4*>(&Bs[kk][(tid & 15) * 8]);
            float4 b1 = *reinterpret_cast<const float4*>(&Bs[kk][(tid & 15) * 8 + 4]);
            float a[8] = {a0.x, a0.y, a0.z, a0.w, a1.x, a1.y, a1.z, a1.w};
            float b[8] = {b0.x, b0.y, b0.z, b0.w, b1.x, b1.y, b1.z, b1.w};
            #pragma unroll
            for (int i = 0; i < 8; i++)
                #pragma unroll
                for (int j = 0; j < 8; j++) acc[i][j] += a[i] * b[j];
        }
    }
}

// ---------------- general tiled GEMM (panel TRSM / SYRK / residual) --------
template <int BT, int MODE>
__global__ __launch_bounds__(256)
void gemm_kernel(const float* __restrict__ A, int lda,
                 const float* __restrict__ B, int ldb,
                 float* __restrict__ C, int ldc, int K, int triSkip,
                 const float* __restrict__ D,
                 const float* __restrict__ E) {
    const int bx = blockIdx.x, by = blockIdx.y;
    if (triSkip && by < bx) return;
    const int r0 = by * 128, c0 = bx * 128;

    __shared__ float As[16][132];
    __shared__ float Bs[16][132];

    const int tid = threadIdx.x;        // 256
    const int tx = tid & 15, ty = tid >> 4;
    const int ai = tid >> 1;
    const int aw = (tid & 1) << 3;

    float acc[8][8];
    #pragma unroll
    for (int i = 0; i < 8; i++)
        #pragma unroll
        for (int j = 0; j < 8; j++) acc[i][j] = 0.0f;

    for (int k0 = 0; k0 < K; k0 += 16) {
        float4 av0 = *reinterpret_cast<const float4*>(
            &A[(size_t)(r0 + ai) * lda + k0 + aw]);
        float4 av1 = *reinterpret_cast<const float4*>(
            &A[(size_t)(r0 + ai) * lda + k0 + aw + 4]);
        float4 bv0, bv1;
        if (BT) {
            bv0 = *reinterpret_cast<const float4*>(
                &B[(size_t)(c0 + ai) * ldb + k0 + aw]);
            bv1 = *reinterpret_cast<const float4*>(
                &B[(size_t)(c0 + ai) * ldb + k0 + aw + 4]);
        } else {
            bv0 = *reinterpret_cast<const float4*>(
                &B[(size_t)(k0 + (tid >> 5)) * ldb + c0 + ((tid & 31) << 2)]);
            bv1 = *reinterpret_cast<const float4*>(
                &B[(size_t)(k0 + 8 + (tid >> 5)) * ldb + c0 + ((tid & 31) << 2)]);
        }
        __syncthreads();
        As[aw + 0][ai] = av0.x; As[aw + 1][ai] = av0.y;
        As[aw + 2][ai] = av0.z; As[aw + 3][ai] = av0.w;
        As[aw + 4][ai] = av1.x; As[aw + 5][ai] = av1.y;
        As[aw + 6][ai] = av1.z; As[aw + 7][ai] = av1.w;
        if (BT) {
            Bs[aw + 0][ai] = bv0.x; Bs[aw + 1][ai] = bv0.y;
            Bs[aw + 2][ai] = bv0.z; Bs[aw + 3][ai] = bv0.w;
            Bs[aw + 4][ai] = bv1.x; Bs[aw + 5][ai] = bv1.y;
            Bs[aw + 6][ai] = bv1.z; Bs[aw + 7][ai] = bv1.w;
        } else {
            *reinterpret_cast<float4*>(&Bs[tid >> 5][(tid & 31) << 2]) = bv0;
            *reinterpret_cast<float4*>(&Bs[(tid >> 5) + 8][(tid & 31) << 2]) = bv1;
        }
        __syncthreads();
        #pragma unroll
        for (int kk = 0; kk < 16; kk++) {
            float4 a0 = *reinterpret_cast<const float4*>(&As[kk][ty * 8]);
            float4 a1 = *reinterpret_cast<const float4*>(&As[kk][ty * 8 + 4]);
            float4 b0 = *reinterpret_cast<const float4*>(&Bs[kk][tx * 8]);
            float4 b1 = *reinterpret_cast<const float4*>(&Bs[kk][tx * 8 + 4]);
            float a[8] = {a0.x, a0.y, a0.z, a0.w, a1.x, a1.y, a1.z, a1.w};
            float b[8] = {b0.x, b0.y, b0.z, b0.w, b1.x, b1.y, b1.z, b1.w};
            #pragma unroll
            for (int i = 0; i < 8; i++)
                #pragma unroll
                for (int j = 0; j < 8; j++) acc[i][j] += a[i] * b[j];
        }
    }

    float c1 = 0.0f, c2 = 0.0f;
    if (MODE == 2) { c1 = g_scal[0]; c2 = g_scal[1]; }
    #pragma unroll
    for (int i = 0; i < 8; i++) {
        size_t base = (size_t)(r0 + ty * 8 + i) * ldc + c0 + tx * 8;
        #pragma unroll
        for (int j = 0; j < 8; j++) {
            if (MODE == 0) C[base + j] -= acc[i][j];
            else if (MODE == 1) C[base + j] = acc[i][j];
            else C[base + j] = D[base + j] - c1 * acc[i][j] - c2 * E[base + j];
        }
    }
}

// ---------------- F/G precompute INTO g_M: one launch, grid (NPAN, NPAN) ---
// For each lower block (i,j), i>j:
//   G_{i,j} = Linv_i * L_{i,j}  -> stored at UPPER block (j,i)
//   F_{i,j} = L_{i,j} * Linv_j  -> stored IN PLACE at (i,j)
// (G computed & written first; F write happens after all reads of L_{i,j}.)
__global__ __launch_bounds__(256) void fg_kernel() {
    const int j = blockIdx.x, i = blockIdx.y;
    if (i <= j) return;
    float* Lij = g_M + (size_t)i * NB * N_DIM + (size_t)j * NB;
    const int tx = threadIdx.x & 15, ty = threadIdx.x >> 4;

    float acc[8][8];
    #pragma unroll
    for (int a = 0; a < 8; a++)
        #pragma unroll
        for (int b = 0; b < 8; b++) acc[a][b] = 0.0f;
    // G = Linv_i (NN) * L_{i,j}
    tile_gemm128<0>(g_Linv + (size_t)i * NB * NB, NB, Lij, N_DIM, acc);
    float* Gdst = g_M + (size_t)j * NB * N_DIM + (size_t)i * NB;  // upper (j,i)
    #pragma unroll
    for (int a = 0; a < 8; a++) {
        size_t base = (size_t)(ty * 8 + a) * N_DIM + tx * 8;
        #pragma unroll
        for (int b = 0; b < 8; b++) Gdst[base + b] = acc[a][b];
    }
    __syncthreads();

    #pragma unroll
    for (int a = 0; a < 8; a++)
        #pragma unroll
        for (int b = 0; b < 8; b++) acc[a][b] = 0.0f;
    // F = L_{i,j} * Linv_j (NN), write in place (all reads of Lij complete
    // after the final barrier inside tile_gemm128)
    tile_gemm128<0>(Lij, N_DIM, g_Linv + (size_t)j * NB * NB, NB, acc);
    #pragma unroll
    for (int a = 0; a < 8; a++) {
        size_t base = (size_t)(ty * 8 + a) * N_DIM + tx * 8;
        #pragma unroll
        for (int b = 0; b < 8; b++) Lij[base + b] = acc[a][b];
    }
}

// ---------------- fused forward-solve step (one launch per k) --------------
// grid (NPAN-k, 4).  bx==0: Xout_k = Xwork_k * Linv_k^T (separate buffer).
// bx>0:  Xwork_{k+bx} -= Xwork_k * F_{k+bx,k}^T.  Both read OLD Xwork_k.
__global__ __launch_bounds__(256)
void fwd_step_kernel(const float* __restrict__ Xwork, float* __restrict__ Xout,
                     int k) {
    const int bx = blockIdx.x, by = blockIdx.y;
    const float* A = Xwork + (size_t)(by * NB) * N_DIM + (size_t)k * NB;
    const float* B; int ldb; float* C; int sub;
    if (bx == 0) {
        B = g_Linv + (size_t)k * NB * NB; ldb = NB;
        C = Xout + (size_t)(by * NB) * N_DIM + (size_t)k * NB; sub = 0;
    } else {
        int t = k + bx;
        B = g_M + (size_t)t * NB * N_DIM + (size_t)k * NB; ldb = N_DIM;  // F_{t,k}
        C = const_cast<float*>(Xwork) + (size_t)(by * NB) * N_DIM + (size_t)t * NB;
        sub = 1;
    }
    float acc[8][8];
    #pragma unroll
    for (int i = 0; i < 8; i++)
        #pragma unroll
        for (int j = 0; j < 8; j++) acc[i][j] = 0.0f;
    tile_gemm128<1>(A, N_DIM, B, ldb, acc);
    const int tx = threadIdx.x & 15, ty = threadIdx.x >> 4;
    #pragma unroll
    for (int i = 0; i < 8; i++) {
        size_t base = (size_t)(ty * 8 + i) * N_DIM + tx * 8;
        #pragma unroll
        for (int j = 0; j < 8; j++) {
            if (sub) C[base + j] -= acc[i][j];
            else C[base + j] = acc[i][j];
        }
    }
}

// ---------------- fused backward-solve step (one launch per k) -------------
// grid (k+1, 4).  bx==k: Zout_k (=|+=) V_k * Linv_k.
// bx<k:  V_bx -= V_k * G_{k,bx}  (G stored at upper block (bx,k)).
__global__ __launch_bounds__(256)
void bwd_step_kernel(const float* __restrict__ V, float* __restrict__ Zout,
                     int k, int accum) {
    const int bx = blockIdx.x, by = blockIdx.y;
    const float* A = V + (size_t)(by * NB) * N_DIM + (size_t)k * NB;
    const float* B; int ldb; float* C; int mode;  // 0: assign/accum, 1: subtract
    if (bx == k) {
        B = g_Linv + (size_t)k * NB * NB; ldb = NB;
        C = Zout + (size_t)(by * NB) * N_DIM + (size_t)k * NB; mode = 0;
    } else {
        B = g_M + (size_t)bx * NB * N_DIM + (size_t)k * NB; ldb = N_DIM;  // G_{k,bx}
        C = const_cast<float*>(V) + (size_t)(by * NB) * N_DIM + (size_t)bx * NB;
        mode = 1;
    }
    float acc[8][8];
    #pragma unroll
    for (int i = 0; i < 8; i++)
        #pragma unroll
        for (int j = 0; j < 8; j++) acc[i][j] = 0.0f;
    tile_gemm128<0>(A, N_DIM, B, ldb, acc);
    const int tx = threadIdx.x & 15, ty = threadIdx.x >> 4;
    #pragma unroll
    for (int i = 0; i < 8; i++) {
        size_t base = (size_t)(ty * 8 + i) * N_DIM + tx * 8;
        #pragma unroll
        for (int j = 0; j < 8; j++) {
            if (mode) C[base + j] -= acc[i][j];
            else if (accum) C[base + j] += acc[i][j];
            else C[base + j] = acc[i][j];
        }
    }
}

// ---------------- finish: denom_i = a * <z_i, k_i>; out = z / denom --------
__global__ void finish_kernel(const float* __restrict__ Kb,
                              const float* __restrict__ a_p,
                              float* __restrict__ out) {
    const int row = blockIdx.x;
    const float* z = &g_X3[(size_t)row * N_DIM];
    const float* kk = &Kb[(size_t)row * N_DIM];
    __shared__ float red[8];
    __shared__ float dsh;
    int tid = threadIdx.x;  // 256
    float s = 0.0f;
    for (int j = tid; j < N_DIM; j += 256) s += z[j] * kk[j];
    #pragma unroll
    for (int o = 16; o > 0; o >>= 1) s += __shfl_down_sync(0xffffffffu, s, o);
    if ((tid & 31) == 0) red[tid >> 5] = s;
    __syncthreads();
    if (tid == 0) {
        float t = 0.0f;
        #pragma unroll
        for (int w = 0; w < 8; w++) t += red[w];
        dsh = 1.0f / (a_p[0] * t);
    }
    __syncthreads();
    float d = dsh;
    for (int j = tid; j < N_DIM; j += 256)
        out[(size_t)row * N_DIM + j] = z[j] * d;
}

// ---------------- host orchestration --------------------------------------
extern "C" void kernel_launch(void* const* d_in, const int* in_sizes, int n_in,
                              void* d_out, int out_size) {
    // Bind inputs BY SIZE (robust to metadata ordering).
    const float* Kb = nullptr;
    const float* Phi = nullptr;
    const float* v1024a = nullptr;
    const float* v1024b = nullptr;
    const float* a_p = nullptr;
    const float* gam = nullptr;
    for (int i = 0; i < n_in; i++) {
        int sz = in_sizes[i];
        const float* p = (const float*)d_in[i];
        if (sz == N_DIM * N_DIM) Phi = p;
        else if (sz == B_DIM * N_DIM) Kb = p;
        else if (sz == 1024) { if (!v1024a) v1024a = p; else v1024b = p; }
        else if (sz == 1) { if (!a_p) a_p = p; else gam = p; }
    }
    (void)out_size;

    const int dynSmem = 128 * 129 * (int)sizeof(float);  // ~66 KB
    cudaFuncSetAttribute(chol_diag_kernel,
                         cudaFuncAttributeMaxDynamicSharedMemorySize, dynSmem);

    float *pM, *pLinv, *pX1, *pX2, *pX3;
    cudaGetSymbolAddress((void**)&pM, g_M);
    cudaGetSymbolAddress((void**)&pLinv, g_Linv);
    cudaGetSymbolAddress((void**)&pX1, g_X1);
    cudaGetSymbolAddress((void**)&pX2, g_X2);
    cudaGetSymbolAddress((void**)&pX3, g_X3);

    scalars_kernel<<<1, 1024>>>(v1024a, v1024b, gam);
    build_M_kernel<<<4096, 256>>>(Phi);

    // blocked right-looking Cholesky
    for (int k = 0; k < NPAN; k++) {
        chol_diag_kernel<<<1, 1024, dynSmem>>>(k);
        int nt = NPAN - 1 - k;
        if (nt > 0) {
            float* A21 = pM + (size_t)(k + 1) * NB * N_DIM + (size_t)k * NB;
            dim3 gp(1, nt);   // panel: L21 = A21 * Linv_k^T (in place)
            gemm_kernel<1, 1><<<gp, 256>>>(A21, N_DIM,
                                           pLinv + (size_t)k * NB * NB, NB, A21,
                                           N_DIM, NB, 0, nullptr, nullptr);
            float* C22 = pM + (size_t)(k + 1) * NB * N_DIM + (size_t)(k + 1) * NB;
            dim3 gs(nt, nt);  // SYRK (lower tiles only)
            gemm_kernel<1, 0><<<gs, 256>>>(A21, N_DIM, A21, N_DIM, C22, N_DIM,
                                           NB, 1, nullptr, nullptr);
        }
    }

    // F (lower, in place) and G (upper) panels: one wide launch
    fg_kernel<<<dim3(NPAN, NPAN), 256>>>();

    // ---- solve 1: Z = K * L^{-T} * L^{-1} ----
    size_t n4 = (size_t)B_DIM * N_DIM / 4;
    copy_kernel<<<1024, 256>>>(pX1, Kb, n4);
    for (int k = 0; k < NPAN; k++)
        fwd_step_kernel<<<dim3(NPAN - k, B_DIM / NB), 256>>>(pX1, pX2, k);
    for (int k = NPAN - 1; k >= 0; k--)
        bwd_step_kernel<<<dim3(k + 1, B_DIM / NB), 256>>>(pX2, pX3, k, 0);

    // ---- iterative refinement: R = K - c1*Z*Phi - c2*Z; solve; Z += E ----
    gemm_kernel<0, 2><<<dim3(N_DIM / NB, B_DIM / NB), 256>>>(
        pX3, N_DIM, Phi, N_DIM, pX1, N_DIM, N_DIM, 0, Kb, pX3);
    for (int k = 0; k < NPAN; k++)
        fwd_step_kernel<<<dim3(NPAN - k, B_DIM / NB), 256>>>(pX1, pX2, k);
    for (int k = NPAN - 1; k >= 0; k--)
        bwd_step_kernel<<<dim3(k + 1, B_DIM / NB), 256>>>(pX2, pX3, k, 1);

    finish_kernel<<<B_DIM, 256>>>(Kb, a_p, (float*)d_out);
}